// round 6
// baseline (speedup 1.0000x reference)
#include <cuda_runtime.h>
#include <cuda_fp16.h>
#include <math.h>

#define NN 50000
#define EE 625000
#define DD 128
#define ROWS_PER_BLOCK 64
#define GEMM_THREADS 256

typedef unsigned long long u64;

// Scratch (device globals — no allocation allowed in kernel_launch)
__device__ int    g_deg[2 * NN];                // [0:NN) fwd in-deg(+self) by dst, [NN:2NN) bwd by src
__device__ __half g_hs_f[(size_t)NN * DD];      // (x@W_fwd) * dinv_f, fp16 (gather payload)
__device__ __half g_hs_b[(size_t)NN * DD];
__device__ float  g_acc_f[(size_t)NN * DD];     // fp32 accumulators, init = hs (self loop, fp32)
__device__ float  g_acc_b[(size_t)NN * DD];

__device__ __forceinline__ u64 pack2(float a, float b) {
    u64 r; asm("mov.b64 %0, {%1, %2};" : "=l"(r) : "f"(a), "f"(b)); return r;
}
__device__ __forceinline__ void unpack2(u64 v, float& a, float& b) {
    asm("mov.b64 {%0, %1}, %2;" : "=f"(a), "=f"(b) : "l"(v));
}
__device__ __forceinline__ void ffma2(u64& d, u64 a, u64 b) {
    asm("fma.rn.f32x2 %0, %1, %2, %3;" : "=l"(d) : "l"(a), "l"(b), "l"(d));
}
__device__ __forceinline__ u64 fmul2(u64 a, u64 b) {
    u64 r; asm("mul.rn.f32x2 %0, %1, %2;" : "=l"(r) : "l"(a), "l"(b)); return r;
}

__global__ void k_init_deg() {
    int i = blockIdx.x * blockDim.x + threadIdx.x;
    if (i < 2 * NN) g_deg[i] = 1;               // self-loop contributes 1
}

// 2 edges per thread for atomic MLP
__global__ void k_count(const int* __restrict__ ei) {
    int b = (blockIdx.x * blockDim.x + threadIdx.x) * 2;
    #pragma unroll
    for (int j = 0; j < 2; j++) {
        int e = b + j;
        if (e < EE) {
            int s = ei[e];
            int d = ei[EE + e];
            atomicAdd(&g_deg[d], 1);            // fwd conv: degree by dst
            atomicAdd(&g_deg[NN + s], 1);       // bwd conv (reversed): by src
        }
    }
}

// Fused dual GEMM + dinv row scale, FFMA2 (f32x2) inner product.
// Writes hs (fp16 gather payload) + acc (fp32 self-loop seed).
__global__ void __launch_bounds__(GEMM_THREADS)
k_gemm(const float* __restrict__ x,
       const float* __restrict__ Wf,
       const float* __restrict__ Wb) {
    extern __shared__ float sm[];
    float* sW = sm;                 // 128*128 floats (64 KB)
    float* sX = sm + DD * DD;       // 64*128 floats (32 KB)
    const int row0 = blockIdx.x * ROWS_PER_BLOCK;
    const int tid  = threadIdx.x;
    const int warp = tid >> 5, lane = tid & 31;

    for (int i = tid; i < ROWS_PER_BLOCK * DD / 4; i += GEMM_THREADS) {
        int r  = i >> 5;
        int gr = row0 + r;
        float4 v = make_float4(0.f, 0.f, 0.f, 0.f);
        if (gr < NN) v = reinterpret_cast<const float4*>(x)[(size_t)gr * 32 + (i & 31)];
        reinterpret_cast<float4*>(sX)[i] = v;
    }

    #pragma unroll
    for (int pass = 0; pass < 2; pass++) {
        const float* W = pass ? Wb : Wf;
        __syncthreads();
        for (int i = tid; i < DD * DD / 4; i += GEMM_THREADS)
            reinterpret_cast<float4*>(sW)[i] = reinterpret_cast<const float4*>(W)[i];
        __syncthreads();

        u64 acc[8][2];
        #pragma unroll
        for (int r = 0; r < 8; r++) { acc[r][0] = pack2(0.f, 0.f); acc[r][1] = acc[r][0]; }

        const float* xbase = sX + (warp * 8) * DD;
        #pragma unroll 2
        for (int k4 = 0; k4 < 32; k4++) {
            float4 xv[8];
            #pragma unroll
            for (int r = 0; r < 8; r++)
                xv[r] = reinterpret_cast<const float4*>(xbase + (size_t)r * DD)[k4];
            #pragma unroll
            for (int kk = 0; kk < 4; kk++) {
                ulonglong2 w2 = reinterpret_cast<const ulonglong2*>(sW)[(k4 * 4 + kk) * 32 + lane];
                #pragma unroll
                for (int r = 0; r < 8; r++) {
                    float xs = (kk == 0) ? xv[r].x : (kk == 1) ? xv[r].y
                             : (kk == 2) ? xv[r].z : xv[r].w;
                    u64 xs2 = pack2(xs, xs);
                    ffma2(acc[r][0], w2.x, xs2);
                    ffma2(acc[r][1], w2.y, xs2);
                }
            }
        }

        __half* hs = pass ? g_hs_b  : g_hs_f;
        float*  ac = pass ? g_acc_b : g_acc_f;
        const int degoff = pass ? NN : 0;
        #pragma unroll
        for (int r = 0; r < 8; r++) {
            int gr = row0 + warp * 8 + r;
            if (gr < NN) {
                float dinv = rsqrtf((float)g_deg[degoff + gr]);
                u64 d2 = pack2(dinv, dinv);
                ulonglong2 o;
                o.x = fmul2(acc[r][0], d2);
                o.y = fmul2(acc[r][1], d2);
                reinterpret_cast<ulonglong2*>(ac)[(size_t)gr * 32 + lane] = o;
                float f0, f1, f2, f3;
                unpack2(o.x, f0, f1);
                unpack2(o.y, f2, f3);
                uint2 hp;
                *reinterpret_cast<__half2*>(&hp.x) = __floats2half2_rn(f0, f1);
                *reinterpret_cast<__half2*>(&hp.y) = __floats2half2_rn(f2, f3);
                reinterpret_cast<uint2*>(hs)[(size_t)gr * 32 + lane] = hp;
            }
        }
    }
}

// One warp per edge, one conv: gather 256B fp16 row of hs[src], red.v4.f32 into acc[dst].
// C==0: fwd (src=ei[0], dst=ei[1]); C==1: bwd (reversed).
template <int C>
__global__ void k_scatter(const int* __restrict__ ei) {
    unsigned gw = (blockIdx.x * blockDim.x + threadIdx.x) >> 5;
    int lane = threadIdx.x & 31;
    if (gw >= (unsigned)EE) return;
    int a = ei[gw];
    int b = ei[EE + gw];
    int s = C ? b : a;
    int d = C ? a : b;
    const uint2* hs = reinterpret_cast<const uint2*>(C ? g_hs_b : g_hs_f);
    float*      acc = C ? g_acc_b : g_acc_f;
    uint2 hp = hs[(size_t)s * 32 + lane];       // 4 halves
    float2 f0 = __half22float2(*reinterpret_cast<__half2*>(&hp.x));
    float2 f1 = __half22float2(*reinterpret_cast<__half2*>(&hp.y));
    float* p = acc + (size_t)d * DD + lane * 4;
    asm volatile("red.global.add.v4.f32 [%0], {%1, %2, %3, %4};"
                 :: "l"(p), "f"(f0.x), "f"(f0.y), "f"(f1.x), "f"(f1.y) : "memory");
}

// out = relu(dinv_f*acc_f + dinv_b*acc_b + b_f + b_b)
__global__ void k_finalize(const float* __restrict__ bf,
                           const float* __restrict__ bb,
                           float* __restrict__ out) {
    int i = blockIdx.x * blockDim.x + threadIdx.x;      // over NN*32 float4s
    if (i >= NN * 32) return;
    int v  = i >> 5;
    int c4 = i & 31;
    float df = rsqrtf((float)g_deg[v]);
    float db = rsqrtf((float)g_deg[NN + v]);
    float4 af = reinterpret_cast<const float4*>(g_acc_f)[i];
    float4 ab = reinterpret_cast<const float4*>(g_acc_b)[i];
    float4 vf = reinterpret_cast<const float4*>(bf)[c4];
    float4 vb = reinterpret_cast<const float4*>(bb)[c4];
    float4 o;
    o.x = fmaxf(af.x * df + ab.x * db + vf.x + vb.x, 0.f);
    o.y = fmaxf(af.y * df + ab.y * db + vf.y + vb.y, 0.f);
    o.z = fmaxf(af.z * df + ab.z * db + vf.z + vb.z, 0.f);
    o.w = fmaxf(af.w * df + ab.w * db + vf.w + vb.w, 0.f);
    reinterpret_cast<float4*>(out)[i] = o;
}

extern "C" void kernel_launch(void* const* d_in, const int* in_sizes, int n_in,
                              void* d_out, int out_size) {
    const float* x  = (const float*)d_in[0];
    const int*   ei = (const int*)  d_in[1];
    const float* Wf = (const float*)d_in[2];
    const float* bf = (const float*)d_in[3];
    const float* Wb = (const float*)d_in[4];
    const float* bb = (const float*)d_in[5];
    float*       out = (float*)d_out;

    const int smem = (DD * DD + ROWS_PER_BLOCK * DD) * (int)sizeof(float); // 96 KB
    cudaFuncSetAttribute(k_gemm, cudaFuncAttributeMaxDynamicSharedMemorySize, smem);

    k_init_deg<<<(2 * NN + 255) / 256, 256>>>();
    k_count<<<(EE / 2 + 255) / 256, 256>>>(ei);
    k_gemm<<<(NN + ROWS_PER_BLOCK - 1) / ROWS_PER_BLOCK, GEMM_THREADS, smem>>>(x, Wf, Wb);
    k_scatter<0><<<(EE * 32u + 255u) / 256u, 256>>>(ei);   // fwd conv (L2-resident phase)
    k_scatter<1><<<(EE * 32u + 255u) / 256u, 256>>>(ei);   // bwd conv
    k_finalize<<<(NN * 32 + 255) / 256, 256>>>(bf, bb, out);
}

// round 7
// speedup vs baseline: 1.1040x; 1.1040x over previous
#include <cuda_runtime.h>
#include <cuda_fp16.h>
#include <math.h>

#define NN 50000
#define EE 625000
#define DD 128
#define ROWS_PER_BLOCK 64
#define GEMM_THREADS 256

typedef unsigned long long u64;

// Scratch (device globals — no allocation allowed in kernel_launch)
__device__ int    g_deg[2 * NN];                // [0:NN) fwd in-deg(+self) by dst, [NN:2NN) bwd by src
__device__ __half g_hs_f[(size_t)NN * DD];      // (x@W_fwd) * dinv_f, fp16 (gather payload)
__device__ __half g_hs_b[(size_t)NN * DD];
__device__ float  g_acc_f[(size_t)NN * DD];     // fp32 accumulators, init = hs (self loop, fp32)
__device__ float  g_acc_b[(size_t)NN * DD];

__device__ __forceinline__ u64 pack2(float a, float b) {
    u64 r; asm("mov.b64 %0, {%1, %2};" : "=l"(r) : "f"(a), "f"(b)); return r;
}
__device__ __forceinline__ void unpack2(u64 v, float& a, float& b) {
    asm("mov.b64 {%0, %1}, %2;" : "=f"(a), "=f"(b) : "l"(v));
}
__device__ __forceinline__ void ffma2(u64& d, u64 a, u64 b) {
    asm("fma.rn.f32x2 %0, %1, %2, %3;" : "=l"(d) : "l"(a), "l"(b), "l"(d));
}
__device__ __forceinline__ u64 fmul2(u64 a, u64 b) {
    u64 r; asm("mul.rn.f32x2 %0, %1, %2;" : "=l"(r) : "l"(a), "l"(b)); return r;
}

__global__ void k_init_deg() {
    int i = blockIdx.x * blockDim.x + threadIdx.x;
    if (i < 2 * NN) g_deg[i] = 1;               // self-loop contributes 1
}

// 2 edges per thread for atomic MLP
__global__ void k_count(const int* __restrict__ ei) {
    int b = (blockIdx.x * blockDim.x + threadIdx.x) * 2;
    #pragma unroll
    for (int j = 0; j < 2; j++) {
        int e = b + j;
        if (e < EE) {
            int s = ei[e];
            int d = ei[EE + e];
            atomicAdd(&g_deg[d], 1);            // fwd conv: degree by dst
            atomicAdd(&g_deg[NN + s], 1);       // bwd conv (reversed): by src
        }
    }
}

// Fused dual GEMM + dinv row scale, FFMA2 (f32x2) inner product.
// Writes hs (fp16 gather payload) + acc (fp32 self-loop seed).
__global__ void __launch_bounds__(GEMM_THREADS)
k_gemm(const float* __restrict__ x,
       const float* __restrict__ Wf,
       const float* __restrict__ Wb) {
    extern __shared__ float sm[];
    float* sW = sm;                 // 128*128 floats (64 KB)
    float* sX = sm + DD * DD;       // 64*128 floats (32 KB)
    const int row0 = blockIdx.x * ROWS_PER_BLOCK;
    const int tid  = threadIdx.x;
    const int warp = tid >> 5, lane = tid & 31;

    for (int i = tid; i < ROWS_PER_BLOCK * DD / 4; i += GEMM_THREADS) {
        int r  = i >> 5;
        int gr = row0 + r;
        float4 v = make_float4(0.f, 0.f, 0.f, 0.f);
        if (gr < NN) v = reinterpret_cast<const float4*>(x)[(size_t)gr * 32 + (i & 31)];
        reinterpret_cast<float4*>(sX)[i] = v;
    }

    #pragma unroll
    for (int pass = 0; pass < 2; pass++) {
        const float* W = pass ? Wb : Wf;
        __syncthreads();
        for (int i = tid; i < DD * DD / 4; i += GEMM_THREADS)
            reinterpret_cast<float4*>(sW)[i] = reinterpret_cast<const float4*>(W)[i];
        __syncthreads();

        u64 acc[8][2];
        #pragma unroll
        for (int r = 0; r < 8; r++) { acc[r][0] = pack2(0.f, 0.f); acc[r][1] = acc[r][0]; }

        const float* xbase = sX + (warp * 8) * DD;
        #pragma unroll 2
        for (int k4 = 0; k4 < 32; k4++) {
            float4 xv[8];
            #pragma unroll
            for (int r = 0; r < 8; r++)
                xv[r] = reinterpret_cast<const float4*>(xbase + (size_t)r * DD)[k4];
            #pragma unroll
            for (int kk = 0; kk < 4; kk++) {
                ulonglong2 w2 = reinterpret_cast<const ulonglong2*>(sW)[(k4 * 4 + kk) * 32 + lane];
                #pragma unroll
                for (int r = 0; r < 8; r++) {
                    float xs = (kk == 0) ? xv[r].x : (kk == 1) ? xv[r].y
                             : (kk == 2) ? xv[r].z : xv[r].w;
                    u64 xs2 = pack2(xs, xs);
                    ffma2(acc[r][0], w2.x, xs2);
                    ffma2(acc[r][1], w2.y, xs2);
                }
            }
        }

        __half* hs = pass ? g_hs_b  : g_hs_f;
        float*  ac = pass ? g_acc_b : g_acc_f;
        const int degoff = pass ? NN : 0;
        #pragma unroll
        for (int r = 0; r < 8; r++) {
            int gr = row0 + warp * 8 + r;
            if (gr < NN) {
                float dinv = rsqrtf((float)g_deg[degoff + gr]);
                u64 d2 = pack2(dinv, dinv);
                ulonglong2 o;
                o.x = fmul2(acc[r][0], d2);
                o.y = fmul2(acc[r][1], d2);
                reinterpret_cast<ulonglong2*>(ac)[(size_t)gr * 32 + lane] = o;
                float f0, f1, f2, f3;
                unpack2(o.x, f0, f1);
                unpack2(o.y, f2, f3);
                uint2 hp;
                *reinterpret_cast<__half2*>(&hp.x) = __floats2half2_rn(f0, f1);
                *reinterpret_cast<__half2*>(&hp.y) = __floats2half2_rn(f2, f3);
                reinterpret_cast<uint2*>(hs)[(size_t)gr * 32 + lane] = hp;
            }
        }
    }
}

// One warp per edge, BOTH convs (fused — 2 independent gather+red chains per warp):
// gather fp16 hs_f[s] -> red.f32 acc_f[d];  gather fp16 hs_b[d] -> red.f32 acc_b[s].
__global__ void k_scatter(const int* __restrict__ ei) {
    unsigned gw = (blockIdx.x * blockDim.x + threadIdx.x) >> 5;
    int lane = threadIdx.x & 31;
    if (gw >= (unsigned)EE) return;
    int s = ei[gw];
    int d = ei[EE + gw];
    const uint2* hsf = reinterpret_cast<const uint2*>(g_hs_f);
    const uint2* hsb = reinterpret_cast<const uint2*>(g_hs_b);
    uint2 hf = hsf[(size_t)s * 32 + lane];      // two independent 256B gathers in flight
    uint2 hb = hsb[(size_t)d * 32 + lane];
    float2 f0 = __half22float2(*reinterpret_cast<__half2*>(&hf.x));
    float2 f1 = __half22float2(*reinterpret_cast<__half2*>(&hf.y));
    float2 g0 = __half22float2(*reinterpret_cast<__half2*>(&hb.x));
    float2 g1 = __half22float2(*reinterpret_cast<__half2*>(&hb.y));
    float* pf = g_acc_f + (size_t)d * DD + lane * 4;
    float* pb = g_acc_b + (size_t)s * DD + lane * 4;
    asm volatile("red.global.add.v4.f32 [%0], {%1, %2, %3, %4};"
                 :: "l"(pf), "f"(f0.x), "f"(f0.y), "f"(f1.x), "f"(f1.y) : "memory");
    asm volatile("red.global.add.v4.f32 [%0], {%1, %2, %3, %4};"
                 :: "l"(pb), "f"(g0.x), "f"(g0.y), "f"(g1.x), "f"(g1.y) : "memory");
}

// out = relu(dinv_f*acc_f + dinv_b*acc_b + b_f + b_b)
__global__ void k_finalize(const float* __restrict__ bf,
                           const float* __restrict__ bb,
                           float* __restrict__ out) {
    int i = blockIdx.x * blockDim.x + threadIdx.x;      // over NN*32 float4s
    if (i >= NN * 32) return;
    int v  = i >> 5;
    int c4 = i & 31;
    float df = rsqrtf((float)g_deg[v]);
    float db = rsqrtf((float)g_deg[NN + v]);
    float4 af = reinterpret_cast<const float4*>(g_acc_f)[i];
    float4 ab = reinterpret_cast<const float4*>(g_acc_b)[i];
    float4 vf = reinterpret_cast<const float4*>(bf)[c4];
    float4 vb = reinterpret_cast<const float4*>(bb)[c4];
    float4 o;
    o.x = fmaxf(af.x * df + ab.x * db + vf.x + vb.x, 0.f);
    o.y = fmaxf(af.y * df + ab.y * db + vf.y + vb.y, 0.f);
    o.z = fmaxf(af.z * df + ab.z * db + vf.z + vb.z, 0.f);
    o.w = fmaxf(af.w * df + ab.w * db + vf.w + vb.w, 0.f);
    reinterpret_cast<float4*>(out)[i] = o;
}

extern "C" void kernel_launch(void* const* d_in, const int* in_sizes, int n_in,
                              void* d_out, int out_size) {
    const float* x  = (const float*)d_in[0];
    const int*   ei = (const int*)  d_in[1];
    const float* Wf = (const float*)d_in[2];
    const float* bf = (const float*)d_in[3];
    const float* Wb = (const float*)d_in[4];
    const float* bb = (const float*)d_in[5];
    float*       out = (float*)d_out;

    const int smem = (DD * DD + ROWS_PER_BLOCK * DD) * (int)sizeof(float); // 96 KB
    cudaFuncSetAttribute(k_gemm, cudaFuncAttributeMaxDynamicSharedMemorySize, smem);

    k_init_deg<<<(2 * NN + 255) / 256, 256>>>();
    k_count<<<(EE / 2 + 255) / 256, 256>>>(ei);
    k_gemm<<<(NN + ROWS_PER_BLOCK - 1) / ROWS_PER_BLOCK, GEMM_THREADS, smem>>>(x, Wf, Wb);
    k_scatter<<<(EE * 32u + 255u) / 256u, 256>>>(ei);    // 1 warp per edge, both convs fused
    k_finalize<<<(NN * 32 + 255) / 256, 256>>>(bf, bb, out);
}

// round 8
// speedup vs baseline: 1.2312x; 1.1153x over previous
#include <cuda_runtime.h>
#include <cuda_fp16.h>
#include <math.h>

#define NN 50000
#define EE 625000
#define DD 128
#define ROWS_PER_BLOCK 64
#define GEMM_THREADS 256

typedef unsigned long long u64;

// Scratch (device globals — no allocation allowed in kernel_launch)
__device__ int    g_deg[2 * NN];                // [0:NN) fwd in-deg(+self) by dst, [NN:2NN) bwd by src
__device__ __half g_hs_f[(size_t)NN * DD];      // (x@W_fwd) * dinv_f, fp16 (gather payload)
__device__ __half g_hs_b[(size_t)NN * DD];
__device__ __half g_acc_f[(size_t)NN * DD];     // fp16 accumulators, init = hs (self loop)
__device__ __half g_acc_b[(size_t)NN * DD];

__device__ __forceinline__ u64 pack2(float a, float b) {
    u64 r; asm("mov.b64 %0, {%1, %2};" : "=l"(r) : "f"(a), "f"(b)); return r;
}
__device__ __forceinline__ void unpack2(u64 v, float& a, float& b) {
    asm("mov.b64 {%0, %1}, %2;" : "=f"(a), "=f"(b) : "l"(v));
}
__device__ __forceinline__ void ffma2(u64& d, u64 a, u64 b) {
    asm("fma.rn.f32x2 %0, %1, %2, %3;" : "=l"(d) : "l"(a), "l"(b), "l"(d));
}
__device__ __forceinline__ u64 fmul2(u64 a, u64 b) {
    u64 r; asm("mul.rn.f32x2 %0, %1, %2;" : "=l"(r) : "l"(a), "l"(b)); return r;
}

__global__ void k_init_deg() {
    int i = blockIdx.x * blockDim.x + threadIdx.x;
    if (i < 2 * NN) g_deg[i] = 1;               // self-loop contributes 1
}

// 2 edges per thread for atomic MLP
__global__ void k_count(const int* __restrict__ ei) {
    int b = (blockIdx.x * blockDim.x + threadIdx.x) * 2;
    #pragma unroll
    for (int j = 0; j < 2; j++) {
        int e = b + j;
        if (e < EE) {
            int s = ei[e];
            int d = ei[EE + e];
            atomicAdd(&g_deg[d], 1);            // fwd conv: degree by dst
            atomicAdd(&g_deg[NN + s], 1);       // bwd conv (reversed): by src
        }
    }
}

// Fused dual GEMM + dinv row scale, FFMA2 (f32x2) inner product.
// Writes fp16 hs (gather payload) + fp16 acc (self-loop seed, same quantization).
__global__ void __launch_bounds__(GEMM_THREADS)
k_gemm(const float* __restrict__ x,
       const float* __restrict__ Wf,
       const float* __restrict__ Wb) {
    extern __shared__ float sm[];
    float* sW = sm;                 // 128*128 floats (64 KB)
    float* sX = sm + DD * DD;       // 64*128 floats (32 KB)
    const int row0 = blockIdx.x * ROWS_PER_BLOCK;
    const int tid  = threadIdx.x;
    const int warp = tid >> 5, lane = tid & 31;

    for (int i = tid; i < ROWS_PER_BLOCK * DD / 4; i += GEMM_THREADS) {
        int r  = i >> 5;
        int gr = row0 + r;
        float4 v = make_float4(0.f, 0.f, 0.f, 0.f);
        if (gr < NN) v = reinterpret_cast<const float4*>(x)[(size_t)gr * 32 + (i & 31)];
        reinterpret_cast<float4*>(sX)[i] = v;
    }

    #pragma unroll
    for (int pass = 0; pass < 2; pass++) {
        const float* W = pass ? Wb : Wf;
        __syncthreads();
        for (int i = tid; i < DD * DD / 4; i += GEMM_THREADS)
            reinterpret_cast<float4*>(sW)[i] = reinterpret_cast<const float4*>(W)[i];
        __syncthreads();

        u64 acc[8][2];
        #pragma unroll
        for (int r = 0; r < 8; r++) { acc[r][0] = pack2(0.f, 0.f); acc[r][1] = acc[r][0]; }

        const float* xbase = sX + (warp * 8) * DD;
        #pragma unroll 2
        for (int k4 = 0; k4 < 32; k4++) {
            float4 xv[8];
            #pragma unroll
            for (int r = 0; r < 8; r++)
                xv[r] = reinterpret_cast<const float4*>(xbase + (size_t)r * DD)[k4];
            #pragma unroll
            for (int kk = 0; kk < 4; kk++) {
                ulonglong2 w2 = reinterpret_cast<const ulonglong2*>(sW)[(k4 * 4 + kk) * 32 + lane];
                #pragma unroll
                for (int r = 0; r < 8; r++) {
                    float xs = (kk == 0) ? xv[r].x : (kk == 1) ? xv[r].y
                             : (kk == 2) ? xv[r].z : xv[r].w;
                    u64 xs2 = pack2(xs, xs);
                    ffma2(acc[r][0], w2.x, xs2);
                    ffma2(acc[r][1], w2.y, xs2);
                }
            }
        }

        __half* hs = pass ? g_hs_b  : g_hs_f;
        __half* ac = pass ? g_acc_b : g_acc_f;
        const int degoff = pass ? NN : 0;
        #pragma unroll
        for (int r = 0; r < 8; r++) {
            int gr = row0 + warp * 8 + r;
            if (gr < NN) {
                float dinv = rsqrtf((float)g_deg[degoff + gr]);
                u64 d2 = pack2(dinv, dinv);
                u64 o0 = fmul2(acc[r][0], d2);
                u64 o1 = fmul2(acc[r][1], d2);
                float f0, f1, f2, f3;
                unpack2(o0, f0, f1);
                unpack2(o1, f2, f3);
                uint2 hp;
                *reinterpret_cast<__half2*>(&hp.x) = __floats2half2_rn(f0, f1);
                *reinterpret_cast<__half2*>(&hp.y) = __floats2half2_rn(f2, f3);
                reinterpret_cast<uint2*>(hs)[(size_t)gr * 32 + lane] = hp;
                reinterpret_cast<uint2*>(ac)[(size_t)gr * 32 + lane] = hp;
            }
        }
    }
}

// One warp per edge, BOTH convs: gather fp16 hs rows, red.f16x2 directly (no cvt).
// gather hs_f[s] -> acc_f[d];  gather hs_b[d] -> acc_b[s].
__global__ void k_scatter(const int* __restrict__ ei) {
    unsigned gw = (blockIdx.x * blockDim.x + threadIdx.x) >> 5;
    int lane = threadIdx.x & 31;
    if (gw >= (unsigned)EE) return;
    int s = ei[gw];
    int d = ei[EE + gw];
    const uint2* hsf = reinterpret_cast<const uint2*>(g_hs_f);
    const uint2* hsb = reinterpret_cast<const uint2*>(g_hs_b);
    uint2 hf = hsf[(size_t)s * 32 + lane];      // two independent 256B gathers in flight
    uint2 hb = hsb[(size_t)d * 32 + lane];
    __half* pf = g_acc_f + (size_t)d * DD + lane * 4;
    __half* pb = g_acc_b + (size_t)s * DD + lane * 4;
    asm volatile("red.global.add.noftz.f16x2 [%0], %1;"     :: "l"(pf),     "r"(hf.x) : "memory");
    asm volatile("red.global.add.noftz.f16x2 [%0+4], %1;"   :: "l"(pf),     "r"(hf.y) : "memory");
    asm volatile("red.global.add.noftz.f16x2 [%0], %1;"     :: "l"(pb),     "r"(hb.x) : "memory");
    asm volatile("red.global.add.noftz.f16x2 [%0+4], %1;"   :: "l"(pb),     "r"(hb.y) : "memory");
}

// out = relu(dinv_f*acc_f + dinv_b*acc_b + b_f + b_b); acc arrays are fp16.
__global__ void k_finalize(const float* __restrict__ bf,
                           const float* __restrict__ bb,
                           float* __restrict__ out) {
    int i = blockIdx.x * blockDim.x + threadIdx.x;      // over NN*32 uint2 (4 halves each)
    if (i >= NN * 32) return;
    int v  = i >> 5;
    int c4 = i & 31;
    float df = rsqrtf((float)g_deg[v]);
    float db = rsqrtf((float)g_deg[NN + v]);
    uint2 haf = reinterpret_cast<const uint2*>(g_acc_f)[i];
    uint2 hab = reinterpret_cast<const uint2*>(g_acc_b)[i];
    float2 af0 = __half22float2(*reinterpret_cast<__half2*>(&haf.x));
    float2 af1 = __half22float2(*reinterpret_cast<__half2*>(&haf.y));
    float2 ab0 = __half22float2(*reinterpret_cast<__half2*>(&hab.x));
    float2 ab1 = __half22float2(*reinterpret_cast<__half2*>(&hab.y));
    float4 vf = reinterpret_cast<const float4*>(bf)[c4];
    float4 vb = reinterpret_cast<const float4*>(bb)[c4];
    float4 o;
    o.x = fmaxf(af0.x * df + ab0.x * db + vf.x + vb.x, 0.f);
    o.y = fmaxf(af0.y * df + ab0.y * db + vf.y + vb.y, 0.f);
    o.z = fmaxf(af1.x * df + ab1.x * db + vf.z + vb.z, 0.f);
    o.w = fmaxf(af1.y * df + ab1.y * db + vf.w + vb.w, 0.f);
    reinterpret_cast<float4*>(out)[i] = o;
}

extern "C" void kernel_launch(void* const* d_in, const int* in_sizes, int n_in,
                              void* d_out, int out_size) {
    const float* x  = (const float*)d_in[0];
    const int*   ei = (const int*)  d_in[1];
    const float* Wf = (const float*)d_in[2];
    const float* bf = (const float*)d_in[3];
    const float* Wb = (const float*)d_in[4];
    const float* bb = (const float*)d_in[5];
    float*       out = (float*)d_out;

    const int smem = (DD * DD + ROWS_PER_BLOCK * DD) * (int)sizeof(float); // 96 KB
    cudaFuncSetAttribute(k_gemm, cudaFuncAttributeMaxDynamicSharedMemorySize, smem);

    k_init_deg<<<(2 * NN + 255) / 256, 256>>>();
    k_count<<<(EE / 2 + 255) / 256, 256>>>(ei);
    k_gemm<<<(NN + ROWS_PER_BLOCK - 1) / ROWS_PER_BLOCK, GEMM_THREADS, smem>>>(x, Wf, Wb);
    k_scatter<<<(EE * 32u + 255u) / 256u, 256>>>(ei);    // 1 warp per edge, both convs fused
    k_finalize<<<(NN * 32 + 255) / 256, 256>>>(bf, bb, out);
}

// round 9
// speedup vs baseline: 1.4788x; 1.2011x over previous
#include <cuda_runtime.h>
#include <cuda_fp16.h>
#include <math.h>

#define NN 50000
#define EE 625000
#define DD 128
#define ROWS_PER_BLOCK 64
#define GEMM_THREADS 256

typedef unsigned long long u64;

// Scratch (device globals — no allocation allowed in kernel_launch)
__device__ int    g_deg[2 * NN];                // [0:NN) fwd in-deg(+self) by dst, [NN:2NN) bwd by src
__device__ __half g_hs_f[(size_t)NN * DD];      // (x@W_fwd) * dinv_f, fp16 (gather payload)
__device__ __half g_hs_b[(size_t)NN * DD];
__device__ __half g_acc_f[(size_t)NN * DD];     // fp16 accumulators, init = hs (self loop)
__device__ __half g_acc_b[(size_t)NN * DD];

__device__ __forceinline__ u64 pack2(float a, float b) {
    u64 r; asm("mov.b64 %0, {%1, %2};" : "=l"(r) : "f"(a), "f"(b)); return r;
}
__device__ __forceinline__ void unpack2(u64 v, float& a, float& b) {
    asm("mov.b64 {%0, %1}, %2;" : "=f"(a), "=f"(b) : "l"(v));
}
__device__ __forceinline__ void ffma2(u64& d, u64 a, u64 b) {
    asm("fma.rn.f32x2 %0, %1, %2, %3;" : "=l"(d) : "l"(a), "l"(b), "l"(d));
}
__device__ __forceinline__ u64 fmul2(u64 a, u64 b) {
    u64 r; asm("mul.rn.f32x2 %0, %1, %2;" : "=l"(r) : "l"(a), "l"(b)); return r;
}

__global__ void k_init_deg() {
    int i = blockIdx.x * blockDim.x + threadIdx.x;
    if (i < 2 * NN) g_deg[i] = 1;               // self-loop contributes 1
}

// 4 edges per thread for atomic MLP
__global__ void k_count(const int* __restrict__ ei) {
    int b = (blockIdx.x * blockDim.x + threadIdx.x) * 4;
    #pragma unroll
    for (int j = 0; j < 4; j++) {
        int e = b + j;
        if (e < EE) {
            int s = ei[e];
            int d = ei[EE + e];
            atomicAdd(&g_deg[d], 1);            // fwd conv: degree by dst
            atomicAdd(&g_deg[NN + s], 1);       // bwd conv (reversed): by src
        }
    }
}

// Fused dual GEMM + dinv row scale, FFMA2 (f32x2) inner product.
// Writes fp16 hs (gather payload) + fp16 acc (self-loop seed, same quantization).
__global__ void __launch_bounds__(GEMM_THREADS)
k_gemm(const float* __restrict__ x,
       const float* __restrict__ Wf,
       const float* __restrict__ Wb) {
    extern __shared__ float sm[];
    float* sW = sm;                 // 128*128 floats (64 KB)
    float* sX = sm + DD * DD;       // 64*128 floats (32 KB)
    const int row0 = blockIdx.x * ROWS_PER_BLOCK;
    const int tid  = threadIdx.x;
    const int warp = tid >> 5, lane = tid & 31;

    for (int i = tid; i < ROWS_PER_BLOCK * DD / 4; i += GEMM_THREADS) {
        int r  = i >> 5;
        int gr = row0 + r;
        float4 v = make_float4(0.f, 0.f, 0.f, 0.f);
        if (gr < NN) v = reinterpret_cast<const float4*>(x)[(size_t)gr * 32 + (i & 31)];
        reinterpret_cast<float4*>(sX)[i] = v;
    }

    #pragma unroll
    for (int pass = 0; pass < 2; pass++) {
        const float* W = pass ? Wb : Wf;
        __syncthreads();
        for (int i = tid; i < DD * DD / 4; i += GEMM_THREADS)
            reinterpret_cast<float4*>(sW)[i] = reinterpret_cast<const float4*>(W)[i];
        __syncthreads();

        u64 acc[8][2];
        #pragma unroll
        for (int r = 0; r < 8; r++) { acc[r][0] = pack2(0.f, 0.f); acc[r][1] = acc[r][0]; }

        const float* xbase = sX + (warp * 8) * DD;
        #pragma unroll 2
        for (int k4 = 0; k4 < 32; k4++) {
            float4 xv[8];
            #pragma unroll
            for (int r = 0; r < 8; r++)
                xv[r] = reinterpret_cast<const float4*>(xbase + (size_t)r * DD)[k4];
            #pragma unroll
            for (int kk = 0; kk < 4; kk++) {
                ulonglong2 w2 = reinterpret_cast<const ulonglong2*>(sW)[(k4 * 4 + kk) * 32 + lane];
                #pragma unroll
                for (int r = 0; r < 8; r++) {
                    float xs = (kk == 0) ? xv[r].x : (kk == 1) ? xv[r].y
                             : (kk == 2) ? xv[r].z : xv[r].w;
                    u64 xs2 = pack2(xs, xs);
                    ffma2(acc[r][0], w2.x, xs2);
                    ffma2(acc[r][1], w2.y, xs2);
                }
            }
        }

        __half* hs = pass ? g_hs_b  : g_hs_f;
        __half* ac = pass ? g_acc_b : g_acc_f;
        const int degoff = pass ? NN : 0;
        #pragma unroll
        for (int r = 0; r < 8; r++) {
            int gr = row0 + warp * 8 + r;
            if (gr < NN) {
                float dinv = rsqrtf((float)g_deg[degoff + gr]);
                u64 d2 = pack2(dinv, dinv);
                u64 o0 = fmul2(acc[r][0], d2);
                u64 o1 = fmul2(acc[r][1], d2);
                float f0, f1, f2, f3;
                unpack2(o0, f0, f1);
                unpack2(o1, f2, f3);
                uint2 hp;
                *reinterpret_cast<__half2*>(&hp.x) = __floats2half2_rn(f0, f1);
                *reinterpret_cast<__half2*>(&hp.y) = __floats2half2_rn(f2, f3);
                reinterpret_cast<uint2*>(hs)[(size_t)gr * 32 + lane] = hp;
                reinterpret_cast<uint2*>(ac)[(size_t)gr * 32 + lane] = hp;
            }
        }
    }
}

// 2 edges per warp (16 lanes per edge, 16B per lane), BOTH convs:
// gather hs_f[s] (LDG.128) -> red.v4.f16x2 acc_f[d]; gather hs_b[d] -> red.v4.f16x2 acc_b[s].
__global__ void k_scatter(const int* __restrict__ ei) {
    unsigned t  = blockIdx.x * blockDim.x + threadIdx.x;
    unsigned e  = t >> 4;                       // one edge per 16 lanes
    int lane16  = threadIdx.x & 15;
    if (e >= (unsigned)EE) return;
    int s = ei[e];
    int d = ei[EE + e];
    const uint4* hsf = reinterpret_cast<const uint4*>(g_hs_f);
    const uint4* hsb = reinterpret_cast<const uint4*>(g_hs_b);
    uint4 hf = hsf[(size_t)s * 16 + lane16];    // 8 halves, two independent gathers in flight
    uint4 hb = hsb[(size_t)d * 16 + lane16];
    __half* pf = g_acc_f + (size_t)d * DD + lane16 * 8;
    __half* pb = g_acc_b + (size_t)s * DD + lane16 * 8;
    asm volatile("red.global.add.noftz.v4.f16x2 [%0], {%1, %2, %3, %4};"
                 :: "l"(pf), "r"(hf.x), "r"(hf.y), "r"(hf.z), "r"(hf.w) : "memory");
    asm volatile("red.global.add.noftz.v4.f16x2 [%0], {%1, %2, %3, %4};"
                 :: "l"(pb), "r"(hb.x), "r"(hb.y), "r"(hb.z), "r"(hb.w) : "memory");
}

// out = relu(dinv_f*acc_f + dinv_b*acc_b + b_f + b_b); acc arrays are fp16.
__global__ void k_finalize(const float* __restrict__ bf,
                           const float* __restrict__ bb,
                           float* __restrict__ out) {
    int i = blockIdx.x * blockDim.x + threadIdx.x;      // over NN*32 uint2 (4 halves each)
    if (i >= NN * 32) return;
    int v  = i >> 5;
    int c4 = i & 31;
    float df = rsqrtf((float)g_deg[v]);
    float db = rsqrtf((float)g_deg[NN + v]);
    uint2 haf = reinterpret_cast<const uint2*>(g_acc_f)[i];
    uint2 hab = reinterpret_cast<const uint2*>(g_acc_b)[i];
    float2 af0 = __half22float2(*reinterpret_cast<__half2*>(&haf.x));
    float2 af1 = __half22float2(*reinterpret_cast<__half2*>(&haf.y));
    float2 ab0 = __half22float2(*reinterpret_cast<__half2*>(&hab.x));
    float2 ab1 = __half22float2(*reinterpret_cast<__half2*>(&hab.y));
    float4 vf = reinterpret_cast<const float4*>(bf)[c4];
    float4 vb = reinterpret_cast<const float4*>(bb)[c4];
    float4 o;
    o.x = fmaxf(af0.x * df + ab0.x * db + vf.x + vb.x, 0.f);
    o.y = fmaxf(af0.y * df + ab0.y * db + vf.y + vb.y, 0.f);
    o.z = fmaxf(af1.x * df + ab1.x * db + vf.z + vb.z, 0.f);
    o.w = fmaxf(af1.y * df + ab1.y * db + vf.w + vb.w, 0.f);
    reinterpret_cast<float4*>(out)[i] = o;
}

extern "C" void kernel_launch(void* const* d_in, const int* in_sizes, int n_in,
                              void* d_out, int out_size) {
    const float* x  = (const float*)d_in[0];
    const int*   ei = (const int*)  d_in[1];
    const float* Wf = (const float*)d_in[2];
    const float* bf = (const float*)d_in[3];
    const float* Wb = (const float*)d_in[4];
    const float* bb = (const float*)d_in[5];
    float*       out = (float*)d_out;

    const int smem = (DD * DD + ROWS_PER_BLOCK * DD) * (int)sizeof(float); // 96 KB
    cudaFuncSetAttribute(k_gemm, cudaFuncAttributeMaxDynamicSharedMemorySize, smem);

    k_init_deg<<<(2 * NN + 255) / 256, 256>>>();
    k_count<<<(EE / 4 + 255) / 256, 256>>>(ei);
    k_gemm<<<(NN + ROWS_PER_BLOCK - 1) / ROWS_PER_BLOCK, GEMM_THREADS, smem>>>(x, Wf, Wb);
    k_scatter<<<(EE * 16u + 255u) / 256u, 256>>>(ei);    // 16 lanes per edge, both convs fused
    k_finalize<<<(NN * 32 + 255) / 256, 256>>>(bf, bb, out);
}